// round 2
// baseline (speedup 1.0000x reference)
#include <cuda_runtime.h>
#include <cstdint>

// MultiHeadAttentionMap: B=2, H=16, S=2048, D=1024, hd=64
// out = softmax((QK^T + bias) / sqrt(64)) V, heads combined, @ w_out
//
// Round 1: TF32 mma.sync flash attention + TF32 projection GEMM.
// (R0 resubmit after infra failure; sP now aliases dead sQ -> 52KB smem, 4 CTA/SM)

#define S_LEN  2048
#define DMODEL 1024
#define NHEAD  16
#define HDIM   64
#define PAD    68                 // 64 + 4: conflict-free smem fragment loads
#define SMEM_WORDS (3 * 64 * PAD) // sQ(->sP), sK, sV
#define SMEM_BYTES (SMEM_WORDS * 4)

__device__ float g_attn[2u * S_LEN * DMODEL]; // 16 MB scratch (attn before w_out)

__device__ __forceinline__ uint32_t f2tf(float x) {
    uint32_t r;
    asm("cvt.rna.tf32.f32 %0, %1;" : "=r"(r) : "f"(x));
    return r;
}

__device__ __forceinline__ void mma_tf32(float c[4], const uint32_t a[4], const uint32_t b[2]) {
    asm volatile(
        "mma.sync.aligned.m16n8k8.row.col.f32.tf32.tf32.f32 "
        "{%0,%1,%2,%3}, {%4,%5,%6,%7}, {%8,%9}, {%0,%1,%2,%3};\n"
        : "+f"(c[0]), "+f"(c[1]), "+f"(c[2]), "+f"(c[3])
        : "r"(a[0]), "r"(a[1]), "r"(a[2]), "r"(a[3]), "r"(b[0]), "r"(b[1]));
}

// ---------------------------------------------------------------------------
// Flash attention: one CTA per (b, q-tile of 64, h). 4 warps x 16 query rows.
// grid = (2, 32, 16)  [b fastest so both batches share bias tiles in L2]
// ---------------------------------------------------------------------------
__global__ void __launch_bounds__(128)
flash_attn_tf32_kernel(const float* __restrict__ Q, const float* __restrict__ K,
                       const float* __restrict__ V, const float* __restrict__ Bias) {
    extern __shared__ uint32_t sm[];
    uint32_t* sQ = sm;            // dead after prologue; reused as sP
    uint32_t* sK = sm + 64 * PAD;
    uint32_t* sV = sm + 2 * 64 * PAD;
    uint32_t* sP = sm;            // alias of sQ

    const int b  = blockIdx.x;
    const int q0 = blockIdx.y * 64;
    const int h  = blockIdx.z;

    const int tid  = threadIdx.x;
    const int w    = tid >> 5;
    const int lane = tid & 31;
    const int g    = lane >> 2;   // groupID (row within 8)
    const int t    = lane & 3;    // thread-in-group (col quad)
    const int wr   = w * 16;      // this warp's first query row in the tile

    const size_t bh_off = (size_t)b * S_LEN * DMODEL + (size_t)h * HDIM;
    const float* Qb = Q + bh_off + (size_t)q0 * DMODEL;
    const float* Kb = K + bh_off;
    const float* Vb = V + bh_off;
    const float* Bb = Bias + ((size_t)h * S_LEN + q0) * S_LEN; // bias[0,h,q0+..,:]

    // Load Q tile [64 x 64] -> tf32 smem
    for (int i = tid; i < 64 * 16; i += 128) {
        int r = i >> 4, c = (i & 15) << 2;
        float4 v = *(const float4*)(Qb + (size_t)r * DMODEL + c);
        uint32_t* d = sQ + r * PAD + c;
        d[0] = f2tf(v.x); d[1] = f2tf(v.y); d[2] = f2tf(v.z); d[3] = f2tf(v.w);
    }
    __syncthreads();

    // Hoist Q A-fragments (constant over the K loop). 8 k-steps x 4 regs.
    // After this, sQ is dead -> region reused as sP.
    uint32_t aQ[8][4];
    #pragma unroll
    for (int ks = 0; ks < 8; ks++) {
        aQ[ks][0] = sQ[(wr + g)     * PAD + ks * 8 + t];
        aQ[ks][1] = sQ[(wr + g + 8) * PAD + ks * 8 + t];
        aQ[ks][2] = sQ[(wr + g)     * PAD + ks * 8 + t + 4];
        aQ[ks][3] = sQ[(wr + g + 8) * PAD + ks * 8 + t + 4];
    }

    float m0 = -1e30f, m1 = -1e30f, l0 = 0.f, l1 = 0.f;
    float O[8][4];
    #pragma unroll
    for (int n = 0; n < 8; n++) { O[n][0] = 0.f; O[n][1] = 0.f; O[n][2] = 0.f; O[n][3] = 0.f; }

    for (int kt = 0; kt < 32; kt++) {
        const int kn0 = kt * 64;
        __syncthreads();  // all warps done with sQ/aQ reads (kt=0) or sK/sV (kt>0)
        for (int i = tid; i < 64 * 16; i += 128) {
            int r = i >> 4, c = (i & 15) << 2;
            const size_t go = (size_t)(kn0 + r) * DMODEL + c;
            float4 kv = *(const float4*)(Kb + go);
            float4 vv = *(const float4*)(Vb + go);
            uint32_t* dk = sK + r * PAD + c;
            dk[0] = f2tf(kv.x); dk[1] = f2tf(kv.y); dk[2] = f2tf(kv.z); dk[3] = f2tf(kv.w);
            uint32_t* dv = sV + r * PAD + c;
            dv[0] = f2tf(vv.x); dv[1] = f2tf(vv.y); dv[2] = f2tf(vv.z); dv[3] = f2tf(vv.w);
        }
        __syncthreads();

        // S = Q K^T : warp computes [16 x 64] as 8 n-tiles of m16n8k8, K=64 in 8 steps
        float Sf[8][4];
        #pragma unroll
        for (int n = 0; n < 8; n++) {
            Sf[n][0] = 0.f; Sf[n][1] = 0.f; Sf[n][2] = 0.f; Sf[n][3] = 0.f;
            #pragma unroll
            for (int ks = 0; ks < 8; ks++) {
                uint32_t bf[2];
                bf[0] = sK[(n * 8 + g) * PAD + ks * 8 + t];
                bf[1] = sK[(n * 8 + g) * PAD + ks * 8 + t + 4];
                mma_tf32(Sf[n], aQ[ks], bf);
            }
        }

        // bias + scale (NOTE: (S + bias) * 1/sqrt(64)), row-max
        const float* Br0 = Bb + (size_t)(wr + g)     * S_LEN + kn0 + 2 * t;
        const float* Br1 = Bb + (size_t)(wr + g + 8) * S_LEN + kn0 + 2 * t;
        float rm0 = -1e30f, rm1 = -1e30f;
        #pragma unroll
        for (int n = 0; n < 8; n++) {
            float2 b0v = *(const float2*)(Br0 + n * 8);
            float2 b1v = *(const float2*)(Br1 + n * 8);
            Sf[n][0] = (Sf[n][0] + b0v.x) * 0.125f;
            Sf[n][1] = (Sf[n][1] + b0v.y) * 0.125f;
            Sf[n][2] = (Sf[n][2] + b1v.x) * 0.125f;
            Sf[n][3] = (Sf[n][3] + b1v.y) * 0.125f;
            rm0 = fmaxf(rm0, fmaxf(Sf[n][0], Sf[n][1]));
            rm1 = fmaxf(rm1, fmaxf(Sf[n][2], Sf[n][3]));
        }
        rm0 = fmaxf(rm0, __shfl_xor_sync(0xffffffffu, rm0, 1));
        rm0 = fmaxf(rm0, __shfl_xor_sync(0xffffffffu, rm0, 2));
        rm1 = fmaxf(rm1, __shfl_xor_sync(0xffffffffu, rm1, 1));
        rm1 = fmaxf(rm1, __shfl_xor_sync(0xffffffffu, rm1, 2));

        float mn0 = fmaxf(m0, rm0), mn1 = fmaxf(m1, rm1);
        float al0 = __expf(m0 - mn0), al1 = __expf(m1 - mn1);
        float rs0 = 0.f, rs1 = 0.f;
        #pragma unroll
        for (int n = 0; n < 8; n++) {
            float p00 = __expf(Sf[n][0] - mn0);
            float p01 = __expf(Sf[n][1] - mn0);
            float p10 = __expf(Sf[n][2] - mn1);
            float p11 = __expf(Sf[n][3] - mn1);
            rs0 += p00 + p01;
            rs1 += p10 + p11;
            sP[(wr + g)     * PAD + n * 8 + 2 * t]     = f2tf(p00);
            sP[(wr + g)     * PAD + n * 8 + 2 * t + 1] = f2tf(p01);
            sP[(wr + g + 8) * PAD + n * 8 + 2 * t]     = f2tf(p10);
            sP[(wr + g + 8) * PAD + n * 8 + 2 * t + 1] = f2tf(p11);
        }
        rs0 += __shfl_xor_sync(0xffffffffu, rs0, 1);
        rs0 += __shfl_xor_sync(0xffffffffu, rs0, 2);
        rs1 += __shfl_xor_sync(0xffffffffu, rs1, 1);
        rs1 += __shfl_xor_sync(0xffffffffu, rs1, 2);

        m0 = mn0; m1 = mn1;
        l0 = l0 * al0 + rs0;
        l1 = l1 * al1 + rs1;
        #pragma unroll
        for (int n = 0; n < 8; n++) {
            O[n][0] *= al0; O[n][1] *= al0; O[n][2] *= al1; O[n][3] *= al1;
        }
        __syncwarp();  // sP rows [wr, wr+16) are warp-private; warp-scope visibility suffices

        // O += P V : keys are the K dim (8 steps), d is the N dim (8 tiles)
        #pragma unroll
        for (int ks = 0; ks < 8; ks++) {
            uint32_t aP[4];
            aP[0] = sP[(wr + g)     * PAD + ks * 8 + t];
            aP[1] = sP[(wr + g + 8) * PAD + ks * 8 + t];
            aP[2] = sP[(wr + g)     * PAD + ks * 8 + t + 4];
            aP[3] = sP[(wr + g + 8) * PAD + ks * 8 + t + 4];
            #pragma unroll
            for (int n = 0; n < 8; n++) {
                uint32_t bf[2];
                bf[0] = sV[(ks * 8 + t)     * PAD + n * 8 + g];
                bf[1] = sV[(ks * 8 + t + 4) * PAD + n * 8 + g];
                mma_tf32(O[n], aP, bf);
            }
        }
    }

    const float inv0 = 1.0f / l0;
    const float inv1 = 1.0f / l1;
    float* o0 = g_attn + bh_off + (size_t)(q0 + wr + g)     * DMODEL;
    float* o1 = g_attn + bh_off + (size_t)(q0 + wr + g + 8) * DMODEL;
    #pragma unroll
    for (int n = 0; n < 8; n++) {
        *(float2*)(o0 + n * 8 + 2 * t) = make_float2(O[n][0] * inv0, O[n][1] * inv0);
        *(float2*)(o1 + n * 8 + 2 * t) = make_float2(O[n][2] * inv1, O[n][3] * inv1);
    }
}

// ---------------------------------------------------------------------------
// Projection: out[4096,1024] = g_attn[4096,1024] @ w_out[1024,1024], TF32.
// grid = (16 n-tiles, 64 m-tiles), 128 threads, 64x64 CTA tile, K chunks of 64.
// ---------------------------------------------------------------------------
__global__ void __launch_bounds__(128)
proj_tf32_kernel(const float* __restrict__ W, float* __restrict__ out) {
    __shared__ uint32_t sA[64 * PAD];
    __shared__ uint32_t sB[64 * PAD];

    const int n0 = blockIdx.x * 64;
    const int m0 = blockIdx.y * 64;
    const int tid  = threadIdx.x;
    const int w    = tid >> 5;
    const int lane = tid & 31;
    const int g    = lane >> 2;
    const int t    = lane & 3;
    const int wr   = w * 16;

    float O[8][4];
    #pragma unroll
    for (int n = 0; n < 8; n++) { O[n][0] = 0.f; O[n][1] = 0.f; O[n][2] = 0.f; O[n][3] = 0.f; }

    for (int kc = 0; kc < 16; kc++) {
        __syncthreads();
        for (int i = tid; i < 64 * 16; i += 128) {
            int r = i >> 4, c = (i & 15) << 2;
            float4 av = *(const float4*)(g_attn + (size_t)(m0 + r) * DMODEL + kc * 64 + c);
            float4 bv = *(const float4*)(W + (size_t)(kc * 64 + r) * DMODEL + n0 + c);
            uint32_t* da = sA + r * PAD + c;
            da[0] = f2tf(av.x); da[1] = f2tf(av.y); da[2] = f2tf(av.z); da[3] = f2tf(av.w);
            uint32_t* db = sB + r * PAD + c;
            db[0] = f2tf(bv.x); db[1] = f2tf(bv.y); db[2] = f2tf(bv.z); db[3] = f2tf(bv.w);
        }
        __syncthreads();
        #pragma unroll
        for (int ks = 0; ks < 8; ks++) {
            uint32_t aA[4];
            aA[0] = sA[(wr + g)     * PAD + ks * 8 + t];
            aA[1] = sA[(wr + g + 8) * PAD + ks * 8 + t];
            aA[2] = sA[(wr + g)     * PAD + ks * 8 + t + 4];
            aA[3] = sA[(wr + g + 8) * PAD + ks * 8 + t + 4];
            #pragma unroll
            for (int n = 0; n < 8; n++) {
                uint32_t bf[2];
                bf[0] = sB[(ks * 8 + t)     * PAD + n * 8 + g];
                bf[1] = sB[(ks * 8 + t + 4) * PAD + n * 8 + g];
                mma_tf32(O[n], aA, bf);
            }
        }
    }

    float* o0 = out + (size_t)(m0 + wr + g)     * DMODEL + n0;
    float* o1 = out + (size_t)(m0 + wr + g + 8) * DMODEL + n0;
    #pragma unroll
    for (int n = 0; n < 8; n++) {
        *(float2*)(o0 + n * 8 + 2 * t) = make_float2(O[n][0], O[n][1]);
        *(float2*)(o1 + n * 8 + 2 * t) = make_float2(O[n][2], O[n][3]);
    }
}

extern "C" void kernel_launch(void* const* d_in, const int* in_sizes, int n_in,
                              void* d_out, int out_size) {
    (void)in_sizes; (void)n_in; (void)out_size;
    const float* Q    = (const float*)d_in[0];
    const float* K    = (const float*)d_in[1];
    const float* V    = (const float*)d_in[2];
    const float* Bias = (const float*)d_in[3];
    const float* W    = (const float*)d_in[4];
    float* out = (float*)d_out;

    cudaFuncSetAttribute(flash_attn_tf32_kernel,
                         cudaFuncAttributeMaxDynamicSharedMemorySize, SMEM_BYTES);
    flash_attn_tf32_kernel<<<dim3(2, 32, 16), 128, SMEM_BYTES>>>(Q, K, V, Bias);
    proj_tf32_kernel<<<dim3(16, 64), 128>>>(W, out);
}